// round 2
// baseline (speedup 1.0000x reference)
#include <cuda_runtime.h>

// Correlation layer: out[b, di*9+dj, h, w] = sum_c f1[b,c,h,w] * f2[b,c,h+di-4,w+dj-4]
// B=8, C=256, H=64, W=128, R=4, D=81. All fp32.
//
// R2: packed fma.rn.f32x2 accumulation (2 fp32 FMA / instr on sm_103a),
//     CC=8 channel chunks (half the syncs), same 3-di-group / W_R=4 tiling.
//
// grid = (H/4, B, 3), block = (32,4). Each thread: 3(di) x 9(dj) x 4(w)
// outputs held as 3x9x2 packed f32x2 accumulators.

#define NB 8
#define NC 256
#define NH 64
#define NW 128
#define ND 81
#define CC 8
#define NCHUNK (NC / CC)
#define ROWS 6
#define ROWW 136   // 128 + 2*4 halo

typedef unsigned long long ull;

__device__ __forceinline__ void cp_async16(void* sdst, const void* gsrc) {
    unsigned s = (unsigned)__cvta_generic_to_shared(sdst);
    asm volatile("cp.async.ca.shared.global [%0], [%1], 16;" :: "r"(s), "l"(gsrc));
}

__device__ __forceinline__ ull pk(float lo, float hi) {
    ull r;
    asm("mov.b64 %0, {%1, %2};" : "=l"(r) : "f"(lo), "f"(hi));
    return r;
}

__device__ __forceinline__ void fma2(ull& d, ull a, ull b) {
    asm("fma.rn.f32x2 %0, %1, %2, %0;" : "+l"(d) : "l"(a), "l"(b));
}

__device__ __forceinline__ float2 upk(ull v) {
    float2 f;
    asm("mov.b64 {%0, %1}, %2;" : "=f"(f.x), "=f"(f.y) : "l"(v));
    return f;
}

__global__ void __launch_bounds__(128, 3)
corr_kernel(const float* __restrict__ f1, const float* __restrict__ f2,
            float* __restrict__ out)
{
    __shared__ float f2s[2][CC][ROWS][ROWW];

    const int tx = threadIdx.x;          // 0..31
    const int ty = threadIdx.y;          // 0..3
    const int tid = ty * 32 + tx;
    const int h0 = blockIdx.x * 4;
    const int b  = blockIdx.y;
    const int g  = blockIdx.z;           // di group: di = 3g + i, i in 0..2
    const int h  = h0 + ty;
    const int w0 = tx * 4;
    const int rowbase = h0 + 3 * g - 4;  // global row of smem slot r=0

    // Zero all smem once. Valid rows are overwritten each chunk; rows that are
    // out-of-image and the +-4 w halos stay zero for the whole kernel.
    for (int i = tid; i < 2 * CC * ROWS * ROWW; i += 128)
        ((float*)f2s)[i] = 0.0f;
    __syncthreads();

    ull acc[3][9][2];    // [di][dj][w-pair]: pair0 = (w0,w1), pair1 = (w2,w3)
    #pragma unroll
    for (int i = 0; i < 3; i++)
        #pragma unroll
        for (int j = 0; j < 9; j++) {
            acc[i][j][0] = 0ull;
            acc[i][j][1] = 0ull;
        }

    // ---- cooperative loader: CC*6*32 = 1536 float4 tasks, 12/thread ----
    auto load_chunk = [&](int c0, int buf) {
        #pragma unroll
        for (int s = 0; s < (CC * ROWS * 32) / 128; s++) {
            int t  = tid + 128 * s;
            int cc = t / (ROWS * 32);
            int r  = (t / 32) % ROWS;
            int q  = t % 32;
            int gr = rowbase + r;
            if (gr >= 0 && gr < NH) {
                const float* src = f2 + (((b * NC + c0 + cc) * NH + gr) * NW + 4 * q);
                cp_async16(&f2s[buf][cc][r][4 + 4 * q], src);
            }
        }
    };

    // ---- compute: per channel, 3 rows x 9 dj, packed f32x2 FMAs ----
    auto compute_chunk = [&](int c0, int buf) {
        #pragma unroll 2
        for (int cc = 0; cc < CC; cc++) {
            const float4 f1v = *reinterpret_cast<const float4*>(
                f1 + (((b * NC + c0 + cc) * NH + h) * NW + w0));
            const ull A01 = pk(f1v.x, f1v.y);
            const ull A23 = pk(f1v.z, f1v.w);
            #pragma unroll
            for (int i = 0; i < 3; i++) {
                const float* row = &f2s[buf][cc][ty + i][0];
                const float4 wa = *reinterpret_cast<const float4*>(row + w0);
                const float4 wb = *reinterpret_cast<const float4*>(row + w0 + 4);
                const float4 wc = *reinterpret_cast<const float4*>(row + w0 + 8);
                ull P[11];
                P[0]  = pk(wa.x, wa.y);
                P[1]  = pk(wa.y, wa.z);
                P[2]  = pk(wa.z, wa.w);
                P[3]  = pk(wa.w, wb.x);
                P[4]  = pk(wb.x, wb.y);
                P[5]  = pk(wb.y, wb.z);
                P[6]  = pk(wb.z, wb.w);
                P[7]  = pk(wb.w, wc.x);
                P[8]  = pk(wc.x, wc.y);
                P[9]  = pk(wc.y, wc.z);
                P[10] = pk(wc.z, wc.w);
                #pragma unroll
                for (int j = 0; j < 9; j++) {
                    fma2(acc[i][j][0], A01, P[j]);       // w0,w1 use win[j],win[j+1]
                    fma2(acc[i][j][1], A23, P[j + 2]);   // w2,w3 use win[j+2],win[j+3]
                }
            }
        }
    };

    // ---- main loop: double-buffered cp.async pipeline ----
    load_chunk(0, 0);
    asm volatile("cp.async.commit_group;");
    for (int chunk = 0; chunk < NCHUNK; chunk++) {
        const int buf = chunk & 1;
        if (chunk + 1 < NCHUNK) {
            load_chunk((chunk + 1) * CC, buf ^ 1);
            asm volatile("cp.async.commit_group;");
            asm volatile("cp.async.wait_group 1;");
        } else {
            asm volatile("cp.async.wait_group 0;");
        }
        __syncthreads();
        compute_chunk(chunk * CC, buf);
        __syncthreads();
    }

    // ---- epilogue: 27 float4 stores ----
    #pragma unroll
    for (int i = 0; i < 3; i++) {
        const int di = 3 * g + i;
        #pragma unroll
        for (int j = 0; j < 9; j++) {
            const int d = di * 9 + j;
            const float2 lo = upk(acc[i][j][0]);
            const float2 hi = upk(acc[i][j][1]);
            float4 v = make_float4(lo.x, lo.y, hi.x, hi.y);
            *reinterpret_cast<float4*>(
                out + (((b * ND + d) * NH + h) * NW + w0)) = v;
        }
    }
}

extern "C" void kernel_launch(void* const* d_in, const int* in_sizes, int n_in,
                              void* d_out, int out_size) {
    const float* f1 = (const float*)d_in[0];
    const float* f2 = (const float*)d_in[1];
    float* out = (float*)d_out;
    dim3 grid(NH / 4, NB, 3);
    dim3 block(32, 4);
    corr_kernel<<<grid, block>>>(f1, f2, out);
}

// round 3
// speedup vs baseline: 1.4871x; 1.4871x over previous
#include <cuda_runtime.h>

// Correlation layer: out[b, di*9+dj, h, w] = sum_c f1[b,c,h,w] * f2[b,c,h+di-4,w+dj-4]
// B=8, C=256, H=64, W=128, R=4, D=81. All fp32.
//
// R3: revert f32x2 (R2 regression: ptxas lowers it to scalar FFMA + MOVs).
//     Keep R1 structure, but stage f1 through the cp.async double-buffered
//     smem pipeline too — removes the per-channel exposed ~250cyc L2 LDG.
//
// grid = (H/4, B, 3), block = (32,4). Each thread: 3(di) x 9(dj) x 4(w) = 108
// fp32 accumulators. CC=4 channels per pipeline stage.

#define NB 8
#define NC 256
#define NH 64
#define NW 128
#define ND 81
#define CC 4
#define NCHUNK (NC / CC)
#define ROWS 6
#define ROWW 136   // 128 + 2*4 halo

__device__ __forceinline__ void cp_async16(void* sdst, const void* gsrc) {
    unsigned s = (unsigned)__cvta_generic_to_shared(sdst);
    asm volatile("cp.async.ca.shared.global [%0], [%1], 16;" :: "r"(s), "l"(gsrc));
}

__global__ void __launch_bounds__(128, 3)
corr_kernel(const float* __restrict__ f1, const float* __restrict__ f2,
            float* __restrict__ out)
{
    __shared__ float f2s[2][CC][ROWS][ROWW];   // 26112 B
    __shared__ float f1s[2][CC][4][NW];        // 16384 B

    const int tx = threadIdx.x;          // 0..31
    const int ty = threadIdx.y;          // 0..3
    const int tid = ty * 32 + tx;
    const int h0 = blockIdx.x * 4;
    const int b  = blockIdx.y;
    const int g  = blockIdx.z;           // di group: di = 3g + i, i in 0..2
    const int h  = h0 + ty;
    const int w0 = tx * 4;
    const int rowbase = h0 + 3 * g - 4;  // global row of f2 smem slot r=0

    // Zero f2 smem once: rows that are out-of-image and the +-4 w halos stay
    // zero for the whole kernel (their validity is fixed per block).
    for (int i = tid; i < 2 * CC * ROWS * ROWW; i += 128)
        ((float*)f2s)[i] = 0.0f;
    __syncthreads();

    float acc[3][9][4];
    #pragma unroll
    for (int i = 0; i < 3; i++)
        #pragma unroll
        for (int j = 0; j < 9; j++)
            #pragma unroll
            for (int k = 0; k < 4; k++)
                acc[i][j][k] = 0.0f;

    // ---- cooperative loader ----
    // f2: CC*6 rows * 32 float4 = 768 tasks (6/thread)
    // f1: CC*4 rows * 32 float4 = 512 tasks (4/thread)
    auto load_chunk = [&](int c0, int buf) {
        #pragma unroll
        for (int s = 0; s < (CC * ROWS * 32) / 128; s++) {
            int t  = tid + 128 * s;
            int cc = t / (ROWS * 32);
            int r  = (t / 32) % ROWS;
            int q  = t % 32;
            int gr = rowbase + r;
            if (gr >= 0 && gr < NH) {
                const float* src = f2 + (((b * NC + c0 + cc) * NH + gr) * NW + 4 * q);
                cp_async16(&f2s[buf][cc][r][4 + 4 * q], src);
            }
        }
        #pragma unroll
        for (int s = 0; s < (CC * 4 * 32) / 128; s++) {
            int t  = tid + 128 * s;
            int cc = t / (4 * 32);
            int r  = (t / 32) % 4;
            int q  = t % 32;
            const float* src = f1 + (((b * NC + c0 + cc) * NH + h0 + r) * NW + 4 * q);
            cp_async16(&f1s[buf][cc][r][4 * q], src);
        }
    };

    // ---- compute: per channel, 3 di rows, 12-float sliding window, 108 FMA ----
    auto compute_chunk = [&](int buf) {
        #pragma unroll
        for (int cc = 0; cc < CC; cc++) {
            const float4 f1v = *reinterpret_cast<const float4*>(&f1s[buf][cc][ty][w0]);
            #pragma unroll
            for (int i = 0; i < 3; i++) {
                const float* row = &f2s[buf][cc][ty + i][0];
                float4 wa = *reinterpret_cast<const float4*>(row + w0);
                float4 wb = *reinterpret_cast<const float4*>(row + w0 + 4);
                float4 wc = *reinterpret_cast<const float4*>(row + w0 + 8);
                float win[12] = {wa.x, wa.y, wa.z, wa.w,
                                 wb.x, wb.y, wb.z, wb.w,
                                 wc.x, wc.y, wc.z, wc.w};
                #pragma unroll
                for (int j = 0; j < 9; j++) {
                    acc[i][j][0] += f1v.x * win[j];
                    acc[i][j][1] += f1v.y * win[j + 1];
                    acc[i][j][2] += f1v.z * win[j + 2];
                    acc[i][j][3] += f1v.w * win[j + 3];
                }
            }
        }
    };

    // ---- main loop: double-buffered cp.async pipeline ----
    load_chunk(0, 0);
    asm volatile("cp.async.commit_group;");
    for (int chunk = 0; chunk < NCHUNK; chunk++) {
        const int buf = chunk & 1;
        if (chunk + 1 < NCHUNK) {
            // buf^1 was last read in iteration chunk-1, which ended with
            // __syncthreads() -> safe to overwrite.
            load_chunk((chunk + 1) * CC, buf ^ 1);
            asm volatile("cp.async.commit_group;");
            asm volatile("cp.async.wait_group 1;");  // current buf's group done
        } else {
            asm volatile("cp.async.wait_group 0;");
        }
        __syncthreads();
        compute_chunk(buf);
        __syncthreads();
    }

    // ---- epilogue: 27 float4 stores ----
    #pragma unroll
    for (int i = 0; i < 3; i++) {
        const int di = 3 * g + i;
        #pragma unroll
        for (int j = 0; j < 9; j++) {
            const int d = di * 9 + j;
            float4 v = make_float4(acc[i][j][0], acc[i][j][1],
                                   acc[i][j][2], acc[i][j][3]);
            *reinterpret_cast<float4*>(
                out + (((b * ND + d) * NH + h) * NW + w0)) = v;
        }
    }
}

extern "C" void kernel_launch(void* const* d_in, const int* in_sizes, int n_in,
                              void* d_out, int out_size) {
    const float* f1 = (const float*)d_in[0];
    const float* f2 = (const float*)d_in[1];
    float* out = (float*)d_out;
    dim3 grid(NH / 4, NB, 3);
    dim3 block(32, 4);
    corr_kernel<<<grid, block>>>(f1, f2, out);
}

// round 5
// speedup vs baseline: 2.0086x; 1.3507x over previous
#include <cuda_runtime.h>
#include <cuda_fp16.h>
#include <cstdint>

// Correlation layer via band-restricted mma.sync (m16n8k16 fp16, fp32 accum).
// out[b, di*9+dj, h, w] = sum_c f1[b,c,h,w] * f2[b,c,h+di-4,w+dj-4]
// B=8, C=256, H=64, W=128, D=81.
//
// Pass 1: cast f1,f2 fp32 -> fp16, same [b,c,h,w] layout (device globals).
// Pass 2: CTA per (b,h). 8 warps = 8 m16 blocks over w. Stream c in chunks of
//   16 (one k16 step) with double-buffered cp.async. smem holds, per chunk,
//   f1 row h [16c x 128w] and the 9 f2 rows h-4..h+4 [16c x (4+128+4)w'],
//   all in natural [c][w] order; ldmatrix .trans produces the fragments.
//   Warp m accumulates, per di, the 3 n8-tiles covering band cols
//   [16m .. 16m+23] (padded-col space = w' + 4). Epilogue: frags -> per-warp
//   smem staging -> out[...][w] = band[w][w+dj]; invalid di stores zeros.

#define NB 8
#define NC 256
#define NH 64
#define NW 128
#define ND 81

#define RSTRIDE 272                 // bytes per c-row in smem (136 halves; 272%128==16 -> LDSM conflict-free)
#define F2ROW (16 * RSTRIDE)        // one f2 row-block (16 c) = 4352 B
#define OFF_F1 (9 * F2ROW)          // f1 block after 9 f2 rows = 39168
#define BUFSZ (OFF_F1 + F2ROW)      // 43520 B per pipeline buffer
#define OFF_STAGE (2 * BUFSZ)       // 87040
#define STAGE_W 25                  // floats per staging row (16 rows/warp)
#define SMEM_SZ (OFF_STAGE + 8 * 16 * STAGE_W * 4)   // 99840 B

__device__ __half g_f1h[(size_t)NB * NC * NH * NW];
__device__ __half g_f2h[(size_t)NB * NC * NH * NW];

// ---------------- fp32 -> fp16 cast (layout-preserving) ----------------
__global__ void cast_kernel(const float4* __restrict__ f1,
                            const float4* __restrict__ f2) {
    const float4* src = blockIdx.y ? f2 : f1;
    __half* dst = blockIdx.y ? g_f2h : g_f1h;
    size_t i0 = (size_t)blockIdx.x * 1024 + threadIdx.x;
    #pragma unroll
    for (int k = 0; k < 4; k++) {
        size_t i = i0 + 256 * k;
        float4 v = src[i];
        __half2 h0 = __floats2half2_rn(v.x, v.y);
        __half2 h1 = __floats2half2_rn(v.z, v.w);
        uint2 o;
        o.x = *reinterpret_cast<uint32_t*>(&h0);
        o.y = *reinterpret_cast<uint32_t*>(&h1);
        reinterpret_cast<uint2*>(dst)[i] = o;
    }
}

// ---------------- PTX helpers ----------------
__device__ __forceinline__ void cpa16(uint32_t dst, const void* src) {
    asm volatile("cp.async.ca.shared.global [%0], [%1], 16;" :: "r"(dst), "l"(src));
}
__device__ __forceinline__ void cpa8(uint32_t dst, const void* src) {
    asm volatile("cp.async.ca.shared.global [%0], [%1], 8;" :: "r"(dst), "l"(src));
}
__device__ __forceinline__ void ldsm4t(uint32_t& r0, uint32_t& r1,
                                       uint32_t& r2, uint32_t& r3, uint32_t a) {
    asm volatile("ldmatrix.sync.aligned.m8n8.x4.trans.shared.b16 {%0,%1,%2,%3}, [%4];"
                 : "=r"(r0), "=r"(r1), "=r"(r2), "=r"(r3) : "r"(a));
}
__device__ __forceinline__ void ldsm2t(uint32_t& r0, uint32_t& r1, uint32_t a) {
    asm volatile("ldmatrix.sync.aligned.m8n8.x2.trans.shared.b16 {%0,%1}, [%2];"
                 : "=r"(r0), "=r"(r1) : "r"(a));
}
__device__ __forceinline__ void mma16816(float* d, uint32_t a0, uint32_t a1,
                                         uint32_t a2, uint32_t a3,
                                         uint32_t b0, uint32_t b1) {
    asm volatile("mma.sync.aligned.m16n8k16.row.col.f32.f16.f16.f32 "
                 "{%0,%1,%2,%3}, {%4,%5,%6,%7}, {%8,%9}, {%0,%1,%2,%3};"
                 : "+f"(d[0]), "+f"(d[1]), "+f"(d[2]), "+f"(d[3])
                 : "r"(a0), "r"(a1), "r"(a2), "r"(a3), "r"(b0), "r"(b1));
}

// ---------------- main kernel ----------------
__global__ void __launch_bounds__(256, 1)
corr_mma(float* __restrict__ out) {
    extern __shared__ char smem[];
    const uint32_t sb = (uint32_t)__cvta_generic_to_shared(smem);
    const int tid = threadIdx.x;
    const int lane = tid & 31, warp = tid >> 5;   // warp = m16 block over w
    const int h = blockIdx.x, b = blockIdx.y;
    const size_t bbase = (size_t)b * NC * NH * NW;

    // Zero the f2 w-halos (padded cols 0-3 and 132-135) in both buffers; the
    // cp.async copies only ever write bytes [8, 264) of each 272B c-row.
    for (int i = tid; i < 2 * 9 * 16; i += 256) {
        int buf = i / 144, rr = i % 144;
        char* row = smem + buf * BUFSZ + rr * RSTRIDE;
        *reinterpret_cast<uint64_t*>(row) = 0ull;        // halves 0-3
        *reinterpret_cast<uint64_t*>(row + 264) = 0ull;  // halves 132-135
    }
    __syncthreads();

    float acc[9][3][4];
    #pragma unroll
    for (int r = 0; r < 9; r++)
        #pragma unroll
        for (int t = 0; t < 3; t++)
            #pragma unroll
            for (int k = 0; k < 4; k++)
                acc[r][t][k] = 0.0f;

    // ldmatrix per-lane address components.
    // A (f1, stored [c][w]): x4 quads = (m0-7,k0-7),(m8-15,k0-7),(m0-7,k8-15),(m8-15,k8-15)
    //   quad q: rows c = (lane%8) + 8*(q>>1), w-offset = 16*warp + 8*(q&1).
    const int q = lane >> 3, lrow = lane & 7;
    const uint32_t a_off = OFF_F1 + (uint32_t)(lrow + ((q >> 1) << 3)) * RSTRIDE
                         + ((16 * warp + ((q & 1) << 3)) << 1);
    // B (f2, stored [c][w'+4]): x2 quads = (k0-7,n0-7),(k8-15,n0-7): rows c = lane%16.
    const uint32_t b_row_off = (uint32_t)(lane & 15) * RSTRIDE;

    // cp.async task decomposition (per chunk):
    //   f2: 9r x 16c x 32 (8B segs)  = 4608 tasks -> 18/thread
    //   f1: 16c x 16 (16B segs)      =  256 tasks -> 1/thread
    auto issue = [&](int cc, int buf) {
        const int c0 = cc * 16;
        const uint32_t dbase = sb + buf * BUFSZ;
        #pragma unroll
        for (int s = 0; s < 18; s++) {
            int t = tid + 256 * s;
            int r = t >> 9, ci = (t >> 5) & 15, sg = t & 31;
            int gr = h + r - 4;
            gr = gr < 0 ? 0 : (gr > NH - 1 ? NH - 1 : gr);   // clamp; invalid di never stored
            const __half* src = g_f2h + bbase + ((size_t)(c0 + ci) * NH + gr) * NW + 4 * sg;
            cpa8(dbase + r * F2ROW + ci * RSTRIDE + 8 + 8 * sg, src);
        }
        {
            int ci = tid >> 4, sg = tid & 15;
            const __half* src = g_f1h + bbase + ((size_t)(c0 + ci) * NH + h) * NW + 8 * sg;
            cpa16(dbase + OFF_F1 + ci * RSTRIDE + 16 * sg, src);
        }
    };

    issue(0, 0);
    asm volatile("cp.async.commit_group;");

    for (int cc = 0; cc < 16; cc++) {
        const int buf = cc & 1;
        if (cc + 1 < 16) {
            issue(cc + 1, buf ^ 1);
            asm volatile("cp.async.commit_group;");
            asm volatile("cp.async.wait_group 1;");
        } else {
            asm volatile("cp.async.wait_group 0;");
        }
        __syncthreads();

        const uint32_t base = sb + buf * BUFSZ;
        uint32_t a0, a1, a2, a3;
        ldsm4t(a0, a1, a2, a3, base + a_off);
        #pragma unroll
        for (int r = 0; r < 9; r++) {
            const uint32_t brow = base + r * F2ROW + b_row_off + 32 * warp;
            #pragma unroll
            for (int t = 0; t < 3; t++) {
                uint32_t b0, b1;
                ldsm2t(b0, b1, brow + 16 * t);   // n8 tile at padded col 16*warp + 8*t
                mma16816(acc[r][t], a0, a1, a2, a3, b0, b1);
            }
        }
        __syncthreads();
    }

    // ---------------- epilogue: band extraction via per-warp staging ----------------
    float* stage = reinterpret_cast<float*>(smem + OFF_STAGE) + warp * 16 * STAGE_W;
    const int gid = lane >> 2, tig = lane & 3;
    const int l16 = lane & 15, dh = lane >> 4;
    #pragma unroll
    for (int r = 0; r < 9; r++) {
        #pragma unroll
        for (int t = 0; t < 3; t++) {
            // d frag: rows gid / gid+8, cols 8t+2tig, +1
            stage[gid * STAGE_W + 8 * t + 2 * tig]           = acc[r][t][0];
            stage[gid * STAGE_W + 8 * t + 2 * tig + 1]       = acc[r][t][1];
            stage[(gid + 8) * STAGE_W + 8 * t + 2 * tig]     = acc[r][t][2];
            stage[(gid + 8) * STAGE_W + 8 * t + 2 * tig + 1] = acc[r][t][3];
        }
        __syncwarp();
        const int gr = h + r - 4;
        const bool valid = (gr >= 0 && gr < NH);
        // out[b, r*9+dj, h, 16*warp + l16] = band[l16][l16 + dj] (padded-col space)
        #pragma unroll
        for (int rd = 0; rd < 5; rd++) {
            int dj = 2 * rd + dh;
            if (dj < 9) {
                float v = valid ? stage[l16 * STAGE_W + l16 + dj] : 0.0f;
                out[(((size_t)b * ND + r * 9 + dj) * NH + h) * NW + 16 * warp + l16] = v;
            }
        }
        __syncwarp();
    }
}

extern "C" void kernel_launch(void* const* d_in, const int* in_sizes, int n_in,
                              void* d_out, int out_size) {
    const float* f1 = (const float*)d_in[0];
    const float* f2 = (const float*)d_in[1];
    float* out = (float*)d_out;

    cudaFuncSetAttribute(corr_mma, cudaFuncAttributeMaxDynamicSharedMemorySize, SMEM_SZ);

    cast_kernel<<<dim3(4096, 2), 256>>>((const float4*)f1, (const float4*)f2);
    corr_mma<<<dim3(NH, NB), 256, SMEM_SZ>>>(out);
}